// round 6
// baseline (speedup 1.0000x reference)
#include <cuda_runtime.h>

#define RADIAL 160
#define RPB 4                          // rows per block
#define ROW_F (RADIAL * 3)             // 480 scalars per row
#define ROW_F4 (ROW_F / 4)             // 120 float4 per row
#define NTHREADS (RPB * ROW_F4)        // 480 threads
#define LPAD 20                        // left zero pad (scalars), mult of 4
#define RPAD 20                        // right zero pad (scalars)
#define SROWF (LPAD + ROW_F + RPAD)    // 520 scalars per stored row
#define SROWF4 (SROWF / 4)             // 130 float4 per stored row

struct Params {
    float dt_offset;
    float dt_persist;
    float k, cc;
    float amount;
    float w[5];
    int   D;
    int   edge;
    int   G;       // uniform float4 window base offset: bf = r4 + G
    int   p;       // uniform alignment phase 0..3
};

__device__ Params g_params;
__device__ float4 g_coefS[ROW_F];      // per-output-scalar fused taps (c0..c3)

__global__ void prep_kernel(const float* __restrict__ offset,
                            const float* __restrict__ persistence,
                            const float* __restrict__ diffusion01,
                            const float* __restrict__ dt_seconds,
                            const float* __restrict__ amount01,
                            const float* __restrict__ spread01) {
    const int s = threadIdx.x;           // 0..479 (one per output scalar)

    float dt = fminf(fmaxf(*dt_seconds, 0.0f), 0.05f);
    float dt_scale = dt * 60.0f;
    float off = (*offset) * dt_scale;
    float P   = powf(*persistence, dt_scale);
    float k   = 0.15f * (*diffusion01);
    float cc  = 1.0f - 2.0f * k;
    int   D   = (int)floorf(off);

    // Edge check over bins 0..159: does floor(i+off) deviate from i+D?
    int myedge = 0;
    if (s < RADIAL) {
        float npi = (float)s + off;
        bool validi = (npi >= 0.0f) && (npi < (float)(RADIAL - 1));
        int lii = min(max((int)floorf(npi), 0), RADIAL - 2);
        myedge = (validi && (lii != s + D)) ? 1 : 0;
    }
    int edge = __syncthreads_or(myedge);

    if (s == 0) {
        g_params.dt_offset  = off;
        g_params.dt_persist = P;
        g_params.k  = k;
        g_params.cc = cc;
        g_params.D  = D;
        g_params.edge = edge;
        g_params.amount = fminf(fmaxf(*amount01, 0.0f), 1.0f);
        float spread = fminf(fmaxf(*spread01, 0.0f), 1.0f);
        float tight  = 1.0f - spread;
        g_params.w[0] = 0.5f + 0.4f * tight;
        g_params.w[1] = 0.2f * spread + 0.05f;
        g_params.w[2] = 0.12f * spread;
        g_params.w[3] = 0.06f * spread;
        g_params.w[4] = 0.02f * spread;
        // Window geometry: store scalar of (r4=0, e=0, d=0) tap = LPAD - 3(D+2)
        int b0 = LPAD - 3 * (D + 2);
        int p  = ((b0 % 4) + 4) % 4;
        g_params.p = p;
        g_params.G = (b0 - p) / 4;       // exact (b0 - p divisible by 4)
    }

    // Fused per-bin coefficients (advect + diffuse + fade), stored per scalar.
    const int bin = s / 3;
    float fade = 1.0f;
    if (bin >= RADIAL - 8) {
        float tt = (float)(RADIAL - 1 - bin) * 0.125f;
        fade = tt * tt;
    }
    float c[4] = {0.0f, 0.0f, 0.0f, 0.0f};
    #pragma unroll
    for (int d = 0; d < 4; d++) {
        int src = bin - D - 2 + d;
        if (src < 0 || src >= RADIAL) continue;
        float nps = (float)src + off;               // same fp ops as reference
        if (!(nps >= 0.0f && nps < (float)(RADIAL - 1))) continue;
        int   ls  = min(max((int)floorf(nps), 0), RADIAL - 2);
        float fr  = nps - (float)ls;
        float wls = (1.0f - fr) * P;
        float wrs = fr * P;
        float sb  = (ls == bin     ? wls : 0.0f) + (ls + 1 == bin     ? wrs : 0.0f);
        float sbm = 0.0f, sbp = 0.0f;
        if (bin >= 1)
            sbm = (ls == bin - 1 ? wls : 0.0f) + (ls + 1 == bin - 1 ? wrs : 0.0f);
        if (bin <= RADIAL - 2)
            sbp = (ls == bin + 1 ? wls : 0.0f) + (ls + 1 == bin + 1 ? wrs : 0.0f);
        c[d] = (cc * sb + k * (sbm + sbp)) * fade;
    }
    g_coefS[s] = make_float4(c[0], c[1], c[2], c[3]);
}

template<int P>
__device__ __forceinline__ float4 apply_taps(const float W[16], const float4* Ct) {
    float4 o;
    float4 c0 = Ct[0], c1 = Ct[1], c2 = Ct[2], c3 = Ct[3];
    o.x = c0.x * W[P + 0] + c0.y * W[P + 3] + c0.z * W[P + 6] + c0.w * W[P + 9];
    o.y = c1.x * W[P + 1] + c1.y * W[P + 4] + c1.z * W[P + 7] + c1.w * W[P + 10];
    o.z = c2.x * W[P + 2] + c2.y * W[P + 5] + c2.z * W[P + 8] + c2.w * W[P + 11];
    o.w = c3.x * W[P + 3] + c3.y * W[P + 6] + c3.z * W[P + 9] + c3.w * W[P + 12];
    return o;
}

__global__ __launch_bounds__(NTHREADS, 3)
void beat_pulse_kernel(const float* __restrict__ history,
                       const float* __restrict__ color_rgb,
                       float* __restrict__ out) {
    __shared__ float s1[RPB * SROWF];   // clipped history w/ zero pads

    const int t = threadIdx.x;
    const long long base_row = (long long)blockIdx.x * RPB;
    const int row = t / ROW_F4;
    const int r4  = t - row * ROW_F4;   // output/input float4 index in row

    // ---- zero pads: 10 float4 per row ----
    if (t < RPB * 10) {
        int r = t / 10;
        int j = t - r * 10;
        int f4 = (j < 5) ? j : (SROWF4 - 5 + (j - 5));
        ((float4*)&s1[r * SROWF])[f4] = make_float4(0.f, 0.f, 0.f, 0.f);
    }

    // ---- Phase 1: coalesced float4 load + inject + clip01 -> SMEM ----
    {
        const float* gin = history + (base_row + row) * ROW_F;
        float4 v = ((const float4*)gin)[r4];
        float vals[4] = {v.x, v.y, v.z, v.w};
        if (r4 < 4) {                    // inject region: scalars [0,15)
            long long b = base_row + row;
            float amount = g_params.amount;
            float en[3];
            en[0] = color_rgb[b * 3 + 0] * amount;
            en[1] = color_rgb[b * 3 + 1] * amount;
            en[2] = color_rgb[b * 3 + 2] * amount;
            #pragma unroll
            for (int e = 0; e < 4; e++) {
                int sidx = r4 * 4 + e;
                int bin  = sidx / 3;
                int ch   = sidx - bin * 3;
                if (bin < 5) vals[e] += en[ch] * g_params.w[bin];
            }
        }
        #pragma unroll
        for (int e = 0; e < 4; e++) vals[e] = fminf(fmaxf(vals[e], 0.0f), 1.0f);
        float4 o; o.x = vals[0]; o.y = vals[1]; o.z = vals[2]; o.w = vals[3];
        ((float4*)&s1[row * SROWF])[(LPAD / 4) + r4] = o;
    }
    __syncthreads();

    if (!g_params.edge) {
        // ---- Fast path: fused 4-tap banded operator on a 16-scalar window ----
        int bf = r4 + g_params.G;
        bf = min(max(bf, 0), SROWF4 - 4);     // clamp => all coefs zero there
        const float4* S4 = (const float4*)&s1[row * SROWF];
        float4 V0 = S4[bf + 0];
        float4 V1 = S4[bf + 1];
        float4 V2 = S4[bf + 2];
        float4 V3 = S4[bf + 3];
        float W[16] = {V0.x, V0.y, V0.z, V0.w,
                       V1.x, V1.y, V1.z, V1.w,
                       V2.x, V2.y, V2.z, V2.w,
                       V3.x, V3.y, V3.z, V3.w};
        const float4* Ct = &g_coefS[4 * r4];

        float4 o;
        switch (g_params.p) {               // uniform branch
            case 0:  o = apply_taps<0>(W, Ct); break;
            case 1:  o = apply_taps<1>(W, Ct); break;
            case 2:  o = apply_taps<2>(W, Ct); break;
            default: o = apply_taps<3>(W, Ct); break;
        }
        ((float4*)(out + (base_row + row) * ROW_F))[r4] = o;
    } else {
        // ---- Generic fallback (never taken for bench params) ----
        const float off = g_params.dt_offset;
        const float P   = g_params.dt_persist;
        const int   D   = g_params.D;

        // Stage A: advect (gather, 4 candidates) into registers.
        float adv[2][3];
        int nloc = 0;
        for (int bb = t; bb < RPB * RADIAL; bb += NTHREADS, nloc++) {
            int rr  = bb / RADIAL;
            int bin = bb - rr * RADIAL;
            const float* s1r = s1 + rr * SROWF + LPAD;
            float wk0 = 0.0f, wk1 = 0.0f, wk2 = 0.0f;
            #pragma unroll
            for (int d = -2; d <= 1; d++) {
                int i = bin - D + d;
                float np = (float)i + off;
                float lf = floorf(np);
                int   li = (int)lf;
                float fr = np - lf;
                bool vs = (i >= 0) & (i < RADIAL) & (np >= 0.0f) & (np < (float)(RADIAL - 1));
                float wl = (vs && li == bin)     ? (1.0f - fr) * P : 0.0f;
                float wr = (vs && li == bin - 1) ? fr * P          : 0.0f;
                float w = wl + wr;
                int a = min(max(i, 0), RADIAL - 1) * 3;
                wk0 += w * s1r[a + 0];
                wk1 += w * s1r[a + 1];
                wk2 += w * s1r[a + 2];
            }
            adv[nloc][0] = wk0; adv[nloc][1] = wk1; adv[nloc][2] = wk2;
        }
        __syncthreads();
        // Stage B: overwrite s1 data region with advected values.
        nloc = 0;
        for (int bb = t; bb < RPB * RADIAL; bb += NTHREADS, nloc++) {
            int rr  = bb / RADIAL;
            int bin = bb - rr * RADIAL;
            float* s1r = s1 + rr * SROWF + LPAD;
            s1r[bin * 3 + 0] = adv[nloc][0];
            s1r[bin * 3 + 1] = adv[nloc][1];
            s1r[bin * 3 + 2] = adv[nloc][2];
        }
        __syncthreads();
        // Stage C: diffusion stencil (zero pads give zero boundary) + fade.
        const float k  = g_params.k;
        const float cc = g_params.cc;
        for (int bb = t; bb < RPB * RADIAL; bb += NTHREADS) {
            int rr  = bb / RADIAL;
            int bin = bb - rr * RADIAL;
            const float* s1r = s1 + rr * SROWF + LPAD;
            float fade = 1.0f;
            if (bin >= RADIAL - 8) {
                float tt = (float)(RADIAL - 1 - bin) * 0.125f;
                fade = tt * tt;
            }
            float* gout = out + (base_row + rr) * ROW_F + bin * 3;
            #pragma unroll
            for (int c = 0; c < 3; c++) {
                float xc = s1r[bin * 3 + c];
                float xm = s1r[(bin - 1) * 3 + c];   // pad -> zero at bin==0
                float xp = s1r[(bin + 1) * 3 + c];   // pad -> zero at bin==159
                gout[c] = (cc * xc + k * xm + k * xp) * fade;
            }
        }
    }
}

extern "C" void kernel_launch(void* const* d_in, const int* in_sizes, int n_in,
                              void* d_out, int out_size) {
    const float* history     = (const float*)d_in[0];
    const float* color_rgb   = (const float*)d_in[1];
    const float* offset      = (const float*)d_in[2];
    const float* persistence = (const float*)d_in[3];
    const float* diffusion01 = (const float*)d_in[4];
    const float* dt_seconds  = (const float*)d_in[5];
    const float* amount01    = (const float*)d_in[6];
    const float* spread01    = (const float*)d_in[7];
    float* out = (float*)d_out;

    int B = in_sizes[0] / ROW_F;
    int grid = (B + RPB - 1) / RPB;

    prep_kernel<<<1, ROW_F>>>(offset, persistence, diffusion01, dt_seconds,
                              amount01, spread01);
    beat_pulse_kernel<<<grid, NTHREADS>>>(history, color_rgb, out);
}

// round 7
// speedup vs baseline: 1.3617x; 1.3617x over previous
#include <cuda_runtime.h>

#define RADIAL 160
#define RPB 4                          // rows per block
#define ROW_F (RADIAL * 3)             // 480 scalars per row
#define ROW_F4 (ROW_F / 4)             // 120 float4 per row
#define NTHREADS (RPB * ROW_F4)        // 480 threads
#define LPAD 20                        // left zero pad (scalars), mult of 4
#define RPAD 20                        // right zero pad (scalars)
#define SROWF (LPAD + ROW_F + RPAD)    // 520 scalars per stored row
#define SROWF4 (SROWF / 4)             // 130 float4 per stored row

struct Params {
    float dt_offset;
    float dt_persist;
    float k, cc;
    float amount;
    float w[5];
    int   D;
    int   edge;
    int   G;       // uniform float4 window base offset: bf = r4 + G
    int   p;       // uniform alignment phase 0..3
};

__device__ Params g_params;
__device__ float g_coefT[4 * ROW_F];   // SoA: g_coefT[d*480 + s] = tap d of scalar s

__global__ void prep_kernel(const float* __restrict__ offset,
                            const float* __restrict__ persistence,
                            const float* __restrict__ diffusion01,
                            const float* __restrict__ dt_seconds,
                            const float* __restrict__ amount01,
                            const float* __restrict__ spread01) {
    const int s = threadIdx.x;           // 0..479 (one per output scalar)

    float dt = fminf(fmaxf(*dt_seconds, 0.0f), 0.05f);
    float dt_scale = dt * 60.0f;
    float off = (*offset) * dt_scale;
    float P   = powf(*persistence, dt_scale);
    float k   = 0.15f * (*diffusion01);
    float cc  = 1.0f - 2.0f * k;
    int   D   = (int)floorf(off);

    // Edge check over bins: does floor(i+off) deviate from i+D?
    int myedge = 0;
    if (s < RADIAL) {
        float npi = (float)s + off;
        bool validi = (npi >= 0.0f) && (npi < (float)(RADIAL - 1));
        int lii = min(max((int)floorf(npi), 0), RADIAL - 2);
        myedge = (validi && (lii != s + D)) ? 1 : 0;
    }
    int edge = __syncthreads_or(myedge);

    if (s == 0) {
        g_params.dt_offset  = off;
        g_params.dt_persist = P;
        g_params.k  = k;
        g_params.cc = cc;
        g_params.D  = D;
        g_params.edge = edge;
        g_params.amount = fminf(fmaxf(*amount01, 0.0f), 1.0f);
        float spread = fminf(fmaxf(*spread01, 0.0f), 1.0f);
        float tight  = 1.0f - spread;
        g_params.w[0] = 0.5f + 0.4f * tight;
        g_params.w[1] = 0.2f * spread + 0.05f;
        g_params.w[2] = 0.12f * spread;
        g_params.w[3] = 0.06f * spread;
        g_params.w[4] = 0.02f * spread;
        // Window geometry: scalar of (r4=0, e=0, d=0) tap = LPAD - 3(D+2)
        int b0 = LPAD - 3 * (D + 2);
        int p  = ((b0 % 4) + 4) % 4;
        g_params.p = p;
        g_params.G = (b0 - p) / 4;       // exact (b0 - p divisible by 4)
    }

    // Fused per-bin coefficients (advect + diffuse + fade), SoA per scalar.
    const int bin = s / 3;
    float fade = 1.0f;
    if (bin >= RADIAL - 8) {
        float tt = (float)(RADIAL - 1 - bin) * 0.125f;
        fade = tt * tt;
    }
    float c[4] = {0.0f, 0.0f, 0.0f, 0.0f};
    #pragma unroll
    for (int d = 0; d < 4; d++) {
        int src = bin - D - 2 + d;
        if (src < 0 || src >= RADIAL) continue;
        float nps = (float)src + off;               // same fp ops as reference
        if (!(nps >= 0.0f && nps < (float)(RADIAL - 1))) continue;
        int   ls  = min(max((int)floorf(nps), 0), RADIAL - 2);
        float fr  = nps - (float)ls;
        float wls = (1.0f - fr) * P;
        float wrs = fr * P;
        float sb  = (ls == bin     ? wls : 0.0f) + (ls + 1 == bin     ? wrs : 0.0f);
        float sbm = 0.0f, sbp = 0.0f;
        if (bin >= 1)
            sbm = (ls == bin - 1 ? wls : 0.0f) + (ls + 1 == bin - 1 ? wrs : 0.0f);
        if (bin <= RADIAL - 2)
            sbp = (ls == bin + 1 ? wls : 0.0f) + (ls + 1 == bin + 1 ? wrs : 0.0f);
        c[d] = (cc * sb + k * (sbm + sbp)) * fade;
    }
    #pragma unroll
    for (int d = 0; d < 4; d++) g_coefT[d * ROW_F + s] = c[d];
}

// Register component selector: scalar J (0..15) of the window {V0,V1,V2,V3}.
template<int J>
__device__ __forceinline__ float getc(const float4 V0, const float4 V1,
                                      const float4 V2, const float4 V3) {
    if constexpr      (J == 0)  return V0.x;
    else if constexpr (J == 1)  return V0.y;
    else if constexpr (J == 2)  return V0.z;
    else if constexpr (J == 3)  return V0.w;
    else if constexpr (J == 4)  return V1.x;
    else if constexpr (J == 5)  return V1.y;
    else if constexpr (J == 6)  return V1.z;
    else if constexpr (J == 7)  return V1.w;
    else if constexpr (J == 8)  return V2.x;
    else if constexpr (J == 9)  return V2.y;
    else if constexpr (J == 10) return V2.z;
    else if constexpr (J == 11) return V2.w;
    else if constexpr (J == 12) return V3.x;
    else if constexpr (J == 13) return V3.y;
    else if constexpr (J == 14) return V3.z;
    else                        return V3.w;
}

// out.e = sum_d Cd.e * W[P + e + 3d]   (all register ops, fully inlined)
template<int P>
__device__ __forceinline__ float4 apply_taps(const float4 V0, const float4 V1,
                                             const float4 V2, const float4 V3,
                                             const float4 C0, const float4 C1,
                                             const float4 C2, const float4 C3) {
    float4 o;
    o.x = C0.x * getc<P + 0>(V0,V1,V2,V3) + C1.x * getc<P + 3>(V0,V1,V2,V3)
        + C2.x * getc<P + 6>(V0,V1,V2,V3) + C3.x * getc<P + 9>(V0,V1,V2,V3);
    o.y = C0.y * getc<P + 1>(V0,V1,V2,V3) + C1.y * getc<P + 4>(V0,V1,V2,V3)
        + C2.y * getc<P + 7>(V0,V1,V2,V3) + C3.y * getc<P + 10>(V0,V1,V2,V3);
    o.z = C0.z * getc<P + 2>(V0,V1,V2,V3) + C1.z * getc<P + 5>(V0,V1,V2,V3)
        + C2.z * getc<P + 8>(V0,V1,V2,V3) + C3.z * getc<P + 11>(V0,V1,V2,V3);
    o.w = C0.w * getc<P + 3>(V0,V1,V2,V3) + C1.w * getc<P + 6>(V0,V1,V2,V3)
        + C2.w * getc<P + 9>(V0,V1,V2,V3) + C3.w * getc<P + 12>(V0,V1,V2,V3);
    return o;
}

__global__ __launch_bounds__(NTHREADS, 3)
void beat_pulse_kernel(const float* __restrict__ history,
                       const float* __restrict__ color_rgb,
                       float* __restrict__ out) {
    __shared__ float s1[RPB * SROWF];      // clipped history w/ zero pads
    __shared__ float scoef[4 * ROW_F];     // SoA coef planes (7.5 KB)

    const int t = threadIdx.x;
    const long long base_row = (long long)blockIdx.x * RPB;
    const int row = t / ROW_F4;
    const int r4  = t - row * ROW_F4;      // float4 index within row

    // ---- stage coef planes into SMEM (coalesced, once per block) ----
    ((float4*)scoef)[t] = ((const float4*)g_coefT)[t];

    // ---- zero pads: 10 float4 per row ----
    if (t < RPB * 10) {
        int r = t / 10;
        int j = t - r * 10;
        int f4 = (j < 5) ? j : (SROWF4 - 5 + (j - 5));
        ((float4*)&s1[r * SROWF])[f4] = make_float4(0.f, 0.f, 0.f, 0.f);
    }

    // ---- Phase 1: coalesced float4 load + inject + clip01 -> SMEM ----
    {
        const float* gin = history + (base_row + row) * ROW_F;
        float4 v = ((const float4*)gin)[r4];
        float vals[4] = {v.x, v.y, v.z, v.w};
        if (r4 < 4) {                       // inject region: scalars [0,15)
            long long b = base_row + row;
            float amount = g_params.amount;
            float en[3];
            en[0] = color_rgb[b * 3 + 0] * amount;
            en[1] = color_rgb[b * 3 + 1] * amount;
            en[2] = color_rgb[b * 3 + 2] * amount;
            #pragma unroll
            for (int e = 0; e < 4; e++) {
                int sidx = r4 * 4 + e;
                int bin  = sidx / 3;
                int ch   = sidx - bin * 3;
                if (bin < 5) vals[e] += en[ch] * g_params.w[bin];
            }
        }
        #pragma unroll
        for (int e = 0; e < 4; e++) vals[e] = fminf(fmaxf(vals[e], 0.0f), 1.0f);
        float4 o; o.x = vals[0]; o.y = vals[1]; o.z = vals[2]; o.w = vals[3];
        ((float4*)&s1[row * SROWF])[(LPAD / 4) + r4] = o;
    }
    __syncthreads();

    if (!g_params.edge) {
        // ---- Fast path: fused 4-tap banded operator, all in registers ----
        int bf = r4 + g_params.G;
        bf = min(max(bf, 0), SROWF4 - 4);       // clamp => all coefs zero there
        const float4* S4 = (const float4*)&s1[row * SROWF];
        float4 V0 = S4[bf + 0];
        float4 V1 = S4[bf + 1];
        float4 V2 = S4[bf + 2];
        float4 V3 = S4[bf + 3];
        // conflict-free stride-16B plane reads
        float4 C0 = ((const float4*)&scoef[0 * ROW_F])[r4];
        float4 C1 = ((const float4*)&scoef[1 * ROW_F])[r4];
        float4 C2 = ((const float4*)&scoef[2 * ROW_F])[r4];
        float4 C3 = ((const float4*)&scoef[3 * ROW_F])[r4];

        float4 o;
        switch (g_params.p) {                   // uniform branch
            case 0:  o = apply_taps<0>(V0,V1,V2,V3,C0,C1,C2,C3); break;
            case 1:  o = apply_taps<1>(V0,V1,V2,V3,C0,C1,C2,C3); break;
            case 2:  o = apply_taps<2>(V0,V1,V2,V3,C0,C1,C2,C3); break;
            default: o = apply_taps<3>(V0,V1,V2,V3,C0,C1,C2,C3); break;
        }
        ((float4*)(out + (base_row + row) * ROW_F))[r4] = o;
    } else {
        // ---- Generic fallback (never taken for bench params) ----
        const float off = g_params.dt_offset;
        const float P   = g_params.dt_persist;
        const int   D   = g_params.D;

        float adv[2][3];
        int nloc = 0;
        for (int bb = t; bb < RPB * RADIAL; bb += NTHREADS, nloc++) {
            int rr  = bb / RADIAL;
            int bin = bb - rr * RADIAL;
            const float* s1r = s1 + rr * SROWF + LPAD;
            float wk0 = 0.0f, wk1 = 0.0f, wk2 = 0.0f;
            #pragma unroll
            for (int d = -2; d <= 1; d++) {
                int i = bin - D + d;
                float np = (float)i + off;
                float lf = floorf(np);
                int   li = (int)lf;
                float fr = np - lf;
                bool vs = (i >= 0) & (i < RADIAL) & (np >= 0.0f) & (np < (float)(RADIAL - 1));
                float wl = (vs && li == bin)     ? (1.0f - fr) * P : 0.0f;
                float wr = (vs && li == bin - 1) ? fr * P          : 0.0f;
                float w = wl + wr;
                int a = min(max(i, 0), RADIAL - 1) * 3;
                wk0 += w * s1r[a + 0];
                wk1 += w * s1r[a + 1];
                wk2 += w * s1r[a + 2];
            }
            adv[nloc][0] = wk0; adv[nloc][1] = wk1; adv[nloc][2] = wk2;
        }
        __syncthreads();
        nloc = 0;
        for (int bb = t; bb < RPB * RADIAL; bb += NTHREADS, nloc++) {
            int rr  = bb / RADIAL;
            int bin = bb - rr * RADIAL;
            float* s1r = s1 + rr * SROWF + LPAD;
            s1r[bin * 3 + 0] = adv[nloc][0];
            s1r[bin * 3 + 1] = adv[nloc][1];
            s1r[bin * 3 + 2] = adv[nloc][2];
        }
        __syncthreads();
        const float k  = g_params.k;
        const float cc = g_params.cc;
        for (int bb = t; bb < RPB * RADIAL; bb += NTHREADS) {
            int rr  = bb / RADIAL;
            int bin = bb - rr * RADIAL;
            const float* s1r = s1 + rr * SROWF + LPAD;
            float fade = 1.0f;
            if (bin >= RADIAL - 8) {
                float tt = (float)(RADIAL - 1 - bin) * 0.125f;
                fade = tt * tt;
            }
            float* gout = out + (base_row + rr) * ROW_F + bin * 3;
            #pragma unroll
            for (int c = 0; c < 3; c++) {
                float xc = s1r[bin * 3 + c];
                float xm = s1r[(bin - 1) * 3 + c];
                float xp = s1r[(bin + 1) * 3 + c];
                gout[c] = (cc * xc + k * xm + k * xp) * fade;
            }
        }
    }
}

extern "C" void kernel_launch(void* const* d_in, const int* in_sizes, int n_in,
                              void* d_out, int out_size) {
    const float* history     = (const float*)d_in[0];
    const float* color_rgb   = (const float*)d_in[1];
    const float* offset      = (const float*)d_in[2];
    const float* persistence = (const float*)d_in[3];
    const float* diffusion01 = (const float*)d_in[4];
    const float* dt_seconds  = (const float*)d_in[5];
    const float* amount01    = (const float*)d_in[6];
    const float* spread01    = (const float*)d_in[7];
    float* out = (float*)d_out;

    int B = in_sizes[0] / ROW_F;
    int grid = (B + RPB - 1) / RPB;

    prep_kernel<<<1, ROW_F>>>(offset, persistence, diffusion01, dt_seconds,
                              amount01, spread01);
    beat_pulse_kernel<<<grid, NTHREADS>>>(history, color_rgb, out);
}